// round 7
// baseline (speedup 1.0000x reference)
#include <cuda_runtime.h>

#define DIM 64
#define KNB 16
#define NREL 33
#define W0PAD 17   // float4 per row -> conflict-free LDS.128

typedef unsigned long long ull;

__device__ __forceinline__ ull pk2(float lo, float hi) {
    ull r; asm("mov.b64 %0, {%1, %2};" : "=l"(r) : "f"(lo), "f"(hi)); return r;
}
__device__ __forceinline__ void fma2(ull& d, ull a, ull b) {
    asm("fma.rn.f32x2 %0, %1, %2, %0;" : "+l"(d) : "l"(a), "l"(b));
}
__device__ __forceinline__ float hadd2(ull v) {
    float lo, hi; asm("mov.b64 {%0, %1}, %2;" : "=f"(lo), "=f"(hi) : "l"(v));
    return lo + hi;
}

__global__ __launch_bounds__(256, 5) void kgnn_kernel(
    const int* __restrict__ u_ids,
    const int* __restrict__ i_ids,
    const int* __restrict__ adj_entity,
    const int* __restrict__ adj_relation,
    const float* __restrict__ user_emb,
    const float* __restrict__ entity_emb,
    const float* __restrict__ relation_emb,
    const float* __restrict__ W0,
    const float* __restrict__ b0,
    const float* __restrict__ W1,
    const float* __restrict__ b1,
    float* __restrict__ out,
    int B)
{
    __shared__ float4 W0_s[64 * W0PAD];
    __shared__ float  ue_s[2][64];
    __shared__ float  ex_s[2][NREL];          // exp(reldot) table
    __shared__ float  attn_s[2][16][16];
    __shared__ float  attn0_s[2][16];
    __shared__ int    e1_s[2][16], r0_s[2][16];
    __shared__ int    e2_s[2][16][16];
    __shared__ __align__(16) float x_s[2][17][64];   // slot 16 = hop-0 vector
    __shared__ __align__(16) float h_s[2][17][64];   // slot 16 = hop-0 hidden
    __shared__ __align__(16) float xf_s[2][64];
    __shared__ float  red_s[2][2];

    const int b    = blockIdx.x;
    const int t    = threadIdx.x;
    const int lane = t & 31;
    const int w    = t >> 5;
    const int bi0  = 2 * b;
    const int bi1  = (2 * b + 1 < B) ? (2 * b + 1) : (B - 1);

    // ---- P1: stage W0, ue x2, hop-0 indices x2 ----
    {
        const float4* W0_4 = (const float4*)W0;
        #pragma unroll
        for (int i = 0; i < 4; i++) {
            int idx = t + i * 256;
            int e = idx >> 4, c = idx & 15;
            W0_s[e * W0PAD + c] = W0_4[idx];
        }
    }
    if (t < 128) {
        const int elem = t >> 6, d = t & 63;
        const int bi = elem ? bi1 : bi0;
        ue_s[elem][d] = user_emb[u_ids[bi] * 64 + d];
    }
    if (t < 32) {
        const int elem = t >> 4, kk = t & 15;
        const int bi = elem ? bi1 : bi0;
        const int e0 = i_ids[bi];
        e1_s[elem][kk] = adj_entity[e0 * KNB + kk];
        r0_s[elem][kk] = adj_relation[e0 * KNB + kk];
    }
    __syncthreads();

    // ---- P2: 66 relation exp-dots + hop-1 index loads (r1 stays in regs) ----
    for (int idx = w; idx < 2 * NREL; idx += 8) {
        const int r = idx >> 1, elem = idx & 1;
        float p = ue_s[elem][lane] * relation_emb[r * 64 + lane]
                + ue_s[elem][lane + 32] * relation_emb[r * 64 + 32 + lane];
        #pragma unroll
        for (int o = 16; o; o >>= 1) p += __shfl_xor_sync(0xffffffffu, p, o);
        if (lane == 0) ex_s[elem][r] = __expf(p * (1.f / 64.f));
    }
    int rr0, rr1;
    {
        const int j = t >> 4, k = t & 15;
        const int ej0 = e1_s[0][j];
        e2_s[0][j][k] = adj_entity[ej0 * KNB + k];
        rr0 = adj_relation[ej0 * KNB + k];
        const int ej1 = e1_s[1][j];
        e2_s[1][j][k] = adj_entity[ej1 * KNB + k];
        rr1 = adj_relation[ej1 * KNB + k];
    }
    __syncthreads();

    // ---- P3: attention: exp lookup + 16-lane sum + divide ----
    {
        const int j = t >> 4, k = t & 15;
        #pragma unroll
        for (int elem = 0; elem < 2; elem++) {
            float ex = ex_s[elem][elem ? rr1 : rr0];
            float sum = ex;
            #pragma unroll
            for (int o = 8; o; o >>= 1) sum += __shfl_xor_sync(0xffffffffu, sum, o);
            attn_s[elem][j][k] = __fdividef(ex, sum * 16.f);
        }
    }
    if (t < 32) {
        const int elem = t >> 4, k = t & 15;
        float ex = ex_s[elem][r0_s[elem][k]];
        float sum = ex;
        #pragma unroll
        for (int o = 8; o; o >>= 1) sum += __shfl_xor_sync(0xffffffffu, sum, o);
        attn0_s[elem][k] = __fdividef(ex, sum * 16.f);
    }
    __syncthreads();

    // ---- P4: float4 entity gathers with packed FMA ----
    const int half = lane >> 4;
    const int c    = lane & 15;
    #pragma unroll
    for (int jj = 0; jj < 4; jj++) {
        const int jg   = w + jj * 8;          // 0..31
        const int elem = jg >> 4, j = jg & 15;
        ull accA = 0ull, accB = 0ull;         // (x,y) and (z,w) packed sums
        #pragma unroll
        for (int kk = 0; kk < 8; kk++) {
            const int k = kk * 2 + half;
            const float4 v = ((const float4*)(entity_emb + e2_s[elem][j][k] * 64))[c];
            const float a = attn_s[elem][j][k];
            const ull ap = pk2(a, a);
            fma2(accA, ap, pk2(v.x, v.y));
            fma2(accB, ap, pk2(v.z, v.w));
        }
        float lo, hi, lo2, hi2;
        asm("mov.b64 {%0, %1}, %2;" : "=f"(lo), "=f"(hi) : "l"(accA));
        asm("mov.b64 {%0, %1}, %2;" : "=f"(lo2), "=f"(hi2) : "l"(accB));
        lo  += __shfl_xor_sync(0xffffffffu, lo, 16);
        hi  += __shfl_xor_sync(0xffffffffu, hi, 16);
        lo2 += __shfl_xor_sync(0xffffffffu, lo2, 16);
        hi2 += __shfl_xor_sync(0xffffffffu, hi2, 16);
        if (half == 0) {
            const float4 sv = ((const float4*)(entity_emb + e1_s[elem][j] * 64))[c];
            ((float4*)x_s[elem][j])[c] = make_float4(sv.x + lo, sv.y + hi,
                                                     sv.z + lo2, sv.w + hi2);
        }
    }
    if (w < 2) {  // hop-0 aggregate -> slot 16
        const int elem = w;
        const int bi = elem ? bi1 : bi0;
        ull accA = 0ull, accB = 0ull;
        #pragma unroll
        for (int kk = 0; kk < 8; kk++) {
            const int k = kk * 2 + half;
            const float4 v = ((const float4*)(entity_emb + e1_s[elem][k] * 64))[c];
            const float a = attn0_s[elem][k];
            const ull ap = pk2(a, a);
            fma2(accA, ap, pk2(v.x, v.y));
            fma2(accB, ap, pk2(v.z, v.w));
        }
        float lo, hi, lo2, hi2;
        asm("mov.b64 {%0, %1}, %2;" : "=f"(lo), "=f"(hi) : "l"(accA));
        asm("mov.b64 {%0, %1}, %2;" : "=f"(lo2), "=f"(hi2) : "l"(accB));
        lo  += __shfl_xor_sync(0xffffffffu, lo, 16);
        hi  += __shfl_xor_sync(0xffffffffu, hi, 16);
        lo2 += __shfl_xor_sync(0xffffffffu, lo2, 16);
        hi2 += __shfl_xor_sync(0xffffffffu, hi2, 16);
        if (half == 0) {
            const float4 sv = ((const float4*)(entity_emb + i_ids[bi] * 64))[c];
            ((float4*)x_s[elem][16])[c] = make_float4(sv.x + lo, sv.y + hi,
                                                      sv.z + lo2, sv.w + hi2);
        }
    }
    __syncthreads();

    // ---- P5: 34 layer-0 matvecs; main pass: warp w -> flat 4w..4w+3 (packed);
    //          second mini-pass: warps 0,1 -> flat 32,33 ----
    {
        const float* xflat = &x_s[0][0][0];
        float*       hflat = &h_s[0][0][0];
        const float bl = b0[lane], bh = b0[lane + 32];
        ull al_[4], ah_[4];
        #pragma unroll
        for (int q = 0; q < 4; q++) { al_[q] = pk2(bl, 0.f); ah_[q] = pk2(bh, 0.f); }
        const int f4 = w * 4;
        #pragma unroll
        for (int dd = 0; dd < 16; dd++) {
            const float4 wl = W0_s[lane * W0PAD + dd];
            const float4 wh = W0_s[(lane + 32) * W0PAD + dd];
            const ull WL0 = pk2(wl.x, wl.y), WL1 = pk2(wl.z, wl.w);
            const ull WH0 = pk2(wh.x, wh.y), WH1 = pk2(wh.z, wh.w);
            #pragma unroll
            for (int q = 0; q < 4; q++) {
                const float4 xv = ((const float4*)(xflat + (f4 + q) * 64))[dd];
                const ull X0 = pk2(xv.x, xv.y), X1 = pk2(xv.z, xv.w);
                fma2(al_[q], X0, WL0); fma2(al_[q], X1, WL1);
                fma2(ah_[q], X0, WH0); fma2(ah_[q], X1, WH1);
            }
        }
        #pragma unroll
        for (int q = 0; q < 4; q++) {
            hflat[(f4 + q) * 64 + lane]      = fmaxf(hadd2(al_[q]), 0.f);
            hflat[(f4 + q) * 64 + lane + 32] = fmaxf(hadd2(ah_[q]), 0.f);
        }
        if (w < 2) {  // leftover flat targets 32, 33
            const int f = 32 + w;
            ull al5 = pk2(bl, 0.f), ah5 = pk2(bh, 0.f);
            #pragma unroll
            for (int dd = 0; dd < 16; dd++) {
                const float4 wl = W0_s[lane * W0PAD + dd];
                const float4 wh = W0_s[(lane + 32) * W0PAD + dd];
                const float4 xv = ((const float4*)(xflat + f * 64))[dd];
                const ull X0 = pk2(xv.x, xv.y), X1 = pk2(xv.z, xv.w);
                fma2(al5, X0, pk2(wl.x, wl.y)); fma2(al5, X1, pk2(wl.z, wl.w));
                fma2(ah5, X0, pk2(wh.x, wh.y)); fma2(ah5, X1, pk2(wh.z, wh.w));
            }
            hflat[f * 64 + lane]      = fmaxf(hadd2(al5), 0.f);
            hflat[f * 64 + lane + 32] = fmaxf(hadd2(ah5), 0.f);
        }
    }
    __syncthreads();

    // ---- P6: layer-1 hop-0 combine (reuses attn0), tanh matvec, score ----
    if (t < 128) {
        const int elem = t >> 6, d = t & 63;
        float agg = 0.f;
        #pragma unroll
        for (int k = 0; k < 16; k++) agg += attn0_s[elem][k] * h_s[elem][k][d];
        xf_s[elem][d] = h_s[elem][16][d] + agg;
    }
    __syncthreads();
    if (t < 128) {
        const int elem = t >> 6, d = t & 63;
        ull acc = pk2(b1[d], 0.f);
        const float4* w1r = (const float4*)(W1 + d * 64);
        const float4* x0v = (const float4*)xf_s[elem];
        #pragma unroll
        for (int dd = 0; dd < 16; dd++) {
            const float4 xv = x0v[dd];
            const float4 wv = w1r[dd];
            fma2(acc, pk2(xv.x, xv.y), pk2(wv.x, wv.y));
            fma2(acc, pk2(xv.z, xv.w), pk2(wv.z, wv.w));
        }
        const float item = tanhf(hadd2(acc));
        float p = ue_s[elem][d] * item;
        #pragma unroll
        for (int o = 16; o; o >>= 1) p += __shfl_xor_sync(0xffffffffu, p, o);
        if (lane == 0) red_s[elem][w & 1] = p;
    }
    __syncthreads();
    if (t < 2) {
        const int bi = 2 * b + t;
        if (bi < B) {
            const float s = red_s[t][0] + red_s[t][1];
            out[bi] = 1.f / (1.f + __expf(-s));
        }
    }
}

extern "C" void kernel_launch(void* const* d_in, const int* in_sizes, int n_in,
                              void* d_out, int out_size) {
    const int*   u_ids        = (const int*)d_in[0];
    const int*   i_ids        = (const int*)d_in[1];
    const int*   adj_entity   = (const int*)d_in[2];
    const int*   adj_relation = (const int*)d_in[3];
    const float* user_emb     = (const float*)d_in[4];
    const float* entity_emb   = (const float*)d_in[5];
    const float* relation_emb = (const float*)d_in[6];
    const float* W0           = (const float*)d_in[7];
    const float* b0           = (const float*)d_in[8];
    const float* W1           = (const float*)d_in[9];
    const float* b1           = (const float*)d_in[10];
    float* out = (float*)d_out;

    const int B = in_sizes[1];
    const int grid = (B + 1) / 2;
    kgnn_kernel<<<grid, 256>>>(u_ids, i_ids, adj_entity, adj_relation,
                               user_emb, entity_emb, relation_emb,
                               W0, b0, W1, b1, out, B);
}

// round 8
// speedup vs baseline: 4.1241x; 4.1241x over previous
#include <cuda_runtime.h>

#define DIM 64
#define KNB 16
#define NREL 33
#define W0PAD 17   // float4 per row -> conflict-free LDS.128

__global__ __launch_bounds__(256, 5) void kgnn_kernel(
    const int* __restrict__ u_ids,
    const int* __restrict__ i_ids,
    const int* __restrict__ adj_entity,
    const int* __restrict__ adj_relation,
    const float* __restrict__ user_emb,
    const float* __restrict__ entity_emb,
    const float* __restrict__ relation_emb,
    const float* __restrict__ W0,
    const float* __restrict__ b0,
    const float* __restrict__ W1,
    const float* __restrict__ b1,
    float* __restrict__ out,
    int B)
{
    __shared__ float4 W0_s[64 * W0PAD];
    __shared__ float  ue_s[2][64];
    __shared__ float  ex_s[2][NREL];          // exp(dot/64) table
    __shared__ float  attn_s[2][16][16];
    __shared__ float  attn0_s[2][16];
    __shared__ int    e1_s[2][16], r0_s[2][16];
    __shared__ int    e2_s[2][16][16];
    __shared__ __align__(16) float x_s[2][17][64];   // slot 16 = hop-0 vector
    __shared__ __align__(16) float h_s[2][17][64];   // slot 16 = hop-0 hidden
    __shared__ __align__(16) float xf_s[2][64];
    __shared__ float  red_s[2][2];

    const int b    = blockIdx.x;
    const int t    = threadIdx.x;
    const int lane = t & 31;
    const int w    = t >> 5;
    const int bi0  = 2 * b;
    const int bi1  = (2 * b + 1 < B) ? (2 * b + 1) : (B - 1);

    // ---- P1: stage W0, ue x2, hop-0 indices x2 ----
    {
        const float4* W0_4 = (const float4*)W0;
        #pragma unroll
        for (int i = 0; i < 4; i++) {
            int idx = t + i * 256;
            int e = idx >> 4, c = idx & 15;
            W0_s[e * W0PAD + c] = W0_4[idx];
        }
    }
    if (t < 128) {
        const int elem = t >> 6, d = t & 63;
        const int bi = elem ? bi1 : bi0;
        ue_s[elem][d] = user_emb[u_ids[bi] * 64 + d];
    }
    if (t < 32) {
        const int elem = t >> 4, kk = t & 15;
        const int bi = elem ? bi1 : bi0;
        const int e0 = i_ids[bi];
        e1_s[elem][kk] = adj_entity[e0 * KNB + kk];
        r0_s[elem][kk] = adj_relation[e0 * KNB + kk];
    }
    __syncthreads();

    // ---- P2: 66 relation exp-dots + hop-1 index loads (r1 in regs) ----
    for (int idx = w; idx < 2 * NREL; idx += 8) {
        const int r = idx >> 1, elem = idx & 1;
        float p = ue_s[elem][lane] * relation_emb[r * 64 + lane]
                + ue_s[elem][lane + 32] * relation_emb[r * 64 + 32 + lane];
        #pragma unroll
        for (int o = 16; o; o >>= 1) p += __shfl_xor_sync(0xffffffffu, p, o);
        if (lane == 0) ex_s[elem][r] = __expf(p * (1.f / 64.f));
    }
    int rr0, rr1;
    {
        const int j = t >> 4, k = t & 15;
        const int ej0 = e1_s[0][j];
        e2_s[0][j][k] = adj_entity[ej0 * KNB + k];
        rr0 = adj_relation[ej0 * KNB + k];
        const int ej1 = e1_s[1][j];
        e2_s[1][j][k] = adj_entity[ej1 * KNB + k];
        rr1 = adj_relation[ej1 * KNB + k];
    }
    __syncthreads();

    // ---- P3: attention: exp lookup + 16-lane sum + divide ----
    {
        const int j = t >> 4, k = t & 15;
        #pragma unroll
        for (int elem = 0; elem < 2; elem++) {
            float ex = ex_s[elem][elem ? rr1 : rr0];
            float sum = ex;
            #pragma unroll
            for (int o = 8; o; o >>= 1) sum += __shfl_xor_sync(0xffffffffu, sum, o);
            attn_s[elem][j][k] = __fdividef(ex, sum * 16.f);
        }
    }
    if (t < 32) {
        const int elem = t >> 4, k = t & 15;
        float ex = ex_s[elem][r0_s[elem][k]];
        float sum = ex;
        #pragma unroll
        for (int o = 8; o; o >>= 1) sum += __shfl_xor_sync(0xffffffffu, sum, o);
        attn0_s[elem][k] = __fdividef(ex, sum * 16.f);
    }
    __syncthreads();

    // ---- P4: float4 entity gathers: 32 j rows + 2 hop-0 rows ----
    const int half = lane >> 4;
    const int c    = lane & 15;
    #pragma unroll
    for (int jj = 0; jj < 4; jj++) {
        const int jg   = w + jj * 8;          // 0..31
        const int elem = jg >> 4, j = jg & 15;
        float4 acc = make_float4(0.f, 0.f, 0.f, 0.f);
        #pragma unroll
        for (int kk = 0; kk < 8; kk++) {
            const int k = kk * 2 + half;
            const float4 v = ((const float4*)(entity_emb + e2_s[elem][j][k] * 64))[c];
            const float a = attn_s[elem][j][k];
            acc.x += a * v.x; acc.y += a * v.y; acc.z += a * v.z; acc.w += a * v.w;
        }
        acc.x += __shfl_xor_sync(0xffffffffu, acc.x, 16);
        acc.y += __shfl_xor_sync(0xffffffffu, acc.y, 16);
        acc.z += __shfl_xor_sync(0xffffffffu, acc.z, 16);
        acc.w += __shfl_xor_sync(0xffffffffu, acc.w, 16);
        if (half == 0) {
            const float4 sv = ((const float4*)(entity_emb + e1_s[elem][j] * 64))[c];
            ((float4*)x_s[elem][j])[c] = make_float4(sv.x + acc.x, sv.y + acc.y,
                                                     sv.z + acc.z, sv.w + acc.w);
        }
    }
    if (w < 2) {  // hop-0 aggregate -> slot 16
        const int elem = w;
        const int bi = elem ? bi1 : bi0;
        float4 acc = make_float4(0.f, 0.f, 0.f, 0.f);
        #pragma unroll
        for (int kk = 0; kk < 8; kk++) {
            const int k = kk * 2 + half;
            const float4 v = ((const float4*)(entity_emb + e1_s[elem][k] * 64))[c];
            const float a = attn0_s[elem][k];
            acc.x += a * v.x; acc.y += a * v.y; acc.z += a * v.z; acc.w += a * v.w;
        }
        acc.x += __shfl_xor_sync(0xffffffffu, acc.x, 16);
        acc.y += __shfl_xor_sync(0xffffffffu, acc.y, 16);
        acc.z += __shfl_xor_sync(0xffffffffu, acc.z, 16);
        acc.w += __shfl_xor_sync(0xffffffffu, acc.w, 16);
        if (half == 0) {
            const float4 sv = ((const float4*)(entity_emb + i_ids[bi] * 64))[c];
            ((float4*)x_s[elem][16])[c] = make_float4(sv.x + acc.x, sv.y + acc.y,
                                                      sv.z + acc.z, sv.w + acc.w);
        }
    }
    __syncthreads();

    // ---- P5: 34 layer-0 matvecs flattened; warp w -> flat 4w..4w+3,
    //          warps 0,1 also take flat 32,33. ----
    {
        const float* xflat = &x_s[0][0][0];
        float*       hflat = &h_s[0][0][0];
        const float bl = b0[lane], bh = b0[lane + 32];
        float al[5], ah[5];
        #pragma unroll
        for (int q = 0; q < 5; q++) { al[q] = bl; ah[q] = bh; }
        const int f4 = w * 4;
        const int f5 = 32 + w;                // valid only for w<2
        const bool has5 = (w < 2);
        #pragma unroll
        for (int dd = 0; dd < 16; dd++) {
            const float4 wl = W0_s[lane * W0PAD + dd];
            const float4 wh = W0_s[(lane + 32) * W0PAD + dd];
            #pragma unroll
            for (int q = 0; q < 4; q++) {
                const float4 xv = ((const float4*)(xflat + (f4 + q) * 64))[dd];
                al[q] += xv.x*wl.x + xv.y*wl.y + xv.z*wl.z + xv.w*wl.w;
                ah[q] += xv.x*wh.x + xv.y*wh.y + xv.z*wh.z + xv.w*wh.w;
            }
            if (has5) {
                const float4 xv = ((const float4*)(xflat + f5 * 64))[dd];
                al[4] += xv.x*wl.x + xv.y*wl.y + xv.z*wl.z + xv.w*wl.w;
                ah[4] += xv.x*wh.x + xv.y*wh.y + xv.z*wh.z + xv.w*wh.w;
            }
        }
        #pragma unroll
        for (int q = 0; q < 4; q++) {
            hflat[(f4 + q) * 64 + lane]      = fmaxf(al[q], 0.f);
            hflat[(f4 + q) * 64 + lane + 32] = fmaxf(ah[q], 0.f);
        }
        if (has5) {
            hflat[f5 * 64 + lane]      = fmaxf(al[4], 0.f);
            hflat[f5 * 64 + lane + 32] = fmaxf(ah[4], 0.f);
        }
    }
    __syncthreads();

    // ---- P6: layer-1 hop-0 combine (reuses attn0), tanh matvec, score ----
    if (t < 128) {
        const int elem = t >> 6, d = t & 63;
        float agg = 0.f;
        #pragma unroll
        for (int k = 0; k < 16; k++) agg += attn0_s[elem][k] * h_s[elem][k][d];
        xf_s[elem][d] = h_s[elem][16][d] + agg;
    }
    __syncthreads();
    if (t < 128) {
        const int elem = t >> 6, d = t & 63;
        float acc = b1[d];
        const float4* w1r = (const float4*)(W1 + d * 64);
        const float4* x0v = (const float4*)xf_s[elem];
        #pragma unroll
        for (int dd = 0; dd < 16; dd++) {
            const float4 xv = x0v[dd];
            const float4 wv = w1r[dd];
            acc += xv.x * wv.x + xv.y * wv.y + xv.z * wv.z + xv.w * wv.w;
        }
        const float item = tanhf(acc);
        float p = ue_s[elem][d] * item;
        #pragma unroll
        for (int o = 16; o; o >>= 1) p += __shfl_xor_sync(0xffffffffu, p, o);
        if (lane == 0) red_s[elem][w & 1] = p;
    }
    __syncthreads();
    if (t < 2) {
        const int bi = 2 * b + t;
        if (bi < B) {
            const float s = red_s[t][0] + red_s[t][1];
            out[bi] = 1.f / (1.f + __expf(-s));
        }
    }
}

extern "C" void kernel_launch(void* const* d_in, const int* in_sizes, int n_in,
                              void* d_out, int out_size) {
    const int*   u_ids        = (const int*)d_in[0];
    const int*   i_ids        = (const int*)d_in[1];
    const int*   adj_entity   = (const int*)d_in[2];
    const int*   adj_relation = (const int*)d_in[3];
    const float* user_emb     = (const float*)d_in[4];
    const float* entity_emb   = (const float*)d_in[5];
    const float* relation_emb = (const float*)d_in[6];
    const float* W0           = (const float*)d_in[7];
    const float* b0           = (const float*)d_in[8];
    const float* W1           = (const float*)d_in[9];
    const float* b1           = (const float*)d_in[10];
    float* out = (float*)d_out;

    const int B = in_sizes[1];
    const int grid = (B + 1) / 2;
    kgnn_kernel<<<grid, 256>>>(u_ids, i_ids, adj_entity, adj_relation,
                               user_emb, entity_emb, relation_emb,
                               W0, b0, W1, b1, out, B);
}

// round 10
// speedup vs baseline: 4.2521x; 1.0310x over previous
#include <cuda_runtime.h>

#define DIM 64
#define KNB 16
#define NREL 33
#define W0PAD 17   // float4 per row -> conflict-free LDS.128

__global__ __launch_bounds__(256, 5) void kgnn_kernel(
    const int* __restrict__ u_ids,
    const int* __restrict__ i_ids,
    const int* __restrict__ adj_entity,
    const int* __restrict__ adj_relation,
    const float* __restrict__ user_emb,
    const float* __restrict__ entity_emb,
    const float* __restrict__ relation_emb,
    const float* __restrict__ W0,
    const float* __restrict__ b0,
    const float* __restrict__ W1,
    const float* __restrict__ b1,
    float* __restrict__ out,
    int B)
{
    // flat groups: g = elem*16 + j for hop-1 (g<32); g = 32+elem for hop-0
    __shared__ float4 W0_s[64 * W0PAD];
    __shared__ float  ue_s[2][64];
    __shared__ float  ex_s[2][NREL];
    __shared__ float  attn_g[34][16];
    __shared__ int    eg_s[34][16];
    __shared__ int    self_s[34];
    __shared__ int    e1_s[2][16], r0_s[2][16];
    __shared__ __align__(16) float x_s[34][64];   // x, then (in-place) h
    __shared__ __align__(16) float xf_s[2][64];
    __shared__ float  red_s[2][2];

    const int b    = blockIdx.x;
    const int t    = threadIdx.x;
    const int lane = t & 31;
    const int w    = t >> 5;
    const int bi0  = 2 * b;
    const int bi1  = (2 * b + 1 < B) ? (2 * b + 1) : (B - 1);

    // ---- P1: stage W0, ue x2, hop-0 indices x2 ----
    {
        const float4* W0_4 = (const float4*)W0;
        #pragma unroll
        for (int i = 0; i < 4; i++) {
            int idx = t + i * 256;
            int e = idx >> 4, c = idx & 15;
            W0_s[e * W0PAD + c] = W0_4[idx];
        }
    }
    if (t < 128) {
        const int elem = t >> 6, d = t & 63;
        const int bi = elem ? bi1 : bi0;
        ue_s[elem][d] = user_emb[u_ids[bi] * 64 + d];
    }
    if (t < 32) {
        const int elem = t >> 4, kk = t & 15;
        const int bi = elem ? bi1 : bi0;
        const int e0 = i_ids[bi];
        e1_s[elem][kk] = adj_entity[e0 * KNB + kk];
        r0_s[elem][kk] = adj_relation[e0 * KNB + kk];
    }
    if (t < 2) self_s[32 + t] = i_ids[t ? bi1 : bi0];
    __syncthreads();

    // ---- P2: 66 relation exp-dots + group tables ----
    for (int idx = w; idx < 2 * NREL; idx += 8) {
        const int r = idx >> 1, elem = idx & 1;
        float p = ue_s[elem][lane] * relation_emb[r * 64 + lane]
                + ue_s[elem][lane + 32] * relation_emb[r * 64 + 32 + lane];
        #pragma unroll
        for (int o = 16; o; o >>= 1) p += __shfl_xor_sync(0xffffffffu, p, o);
        if (lane == 0) ex_s[elem][r] = __expf(p * (1.f / 64.f));
    }
    int rr0, rr1;
    {
        const int j = t >> 4, k = t & 15;
        const int ej0 = e1_s[0][j];
        eg_s[j][k] = adj_entity[ej0 * KNB + k];
        rr0 = adj_relation[ej0 * KNB + k];
        const int ej1 = e1_s[1][j];
        eg_s[16 + j][k] = adj_entity[ej1 * KNB + k];
        rr1 = adj_relation[ej1 * KNB + k];
    }
    if (t < 32) {
        const int elem = t >> 4, j = t & 15;
        self_s[t] = e1_s[0][j];                 // g = 0..15  (elem 0) for t<16;
                                                // t=16..31 writes self_s[16..31] = e1_s[0][j] (overwritten below for elem1)
        eg_s[32 + elem][j] = e1_s[elem][j];     // hop-0 neighbors
    }
    if (t >= 32 && t < 48) self_s[t - 16] = e1_s[1][t - 32];  // g = 16..31 (elem 1)
    __syncthreads();

    // ---- P3: attention: exp lookup + 16-lane sum + divide ----
    {
        const int j = t >> 4, k = t & 15;
        #pragma unroll
        for (int elem = 0; elem < 2; elem++) {
            float ex = ex_s[elem][elem ? rr1 : rr0];
            float sum = ex;
            #pragma unroll
            for (int o = 8; o; o >>= 1) sum += __shfl_xor_sync(0xffffffffu, sum, o);
            attn_g[elem * 16 + j][k] = __fdividef(ex, sum * 16.f);
        }
    }
    if (t < 32) {
        const int elem = t >> 4, k = t & 15;
        float ex = ex_s[elem][r0_s[elem][k]];
        float sum = ex;
        #pragma unroll
        for (int o = 8; o; o >>= 1) sum += __shfl_xor_sync(0xffffffffu, sum, o);
        attn_g[32 + elem][k] = __fdividef(ex, sum * 16.f);
    }
    __syncthreads();

    // ---- P4: unified float4 gathers over 34 groups ----
    const int half = lane >> 4;
    const int c    = lane & 15;
    #pragma unroll
    for (int jj = 0; jj < 4; jj++) {
        const int g = w + jj * 8;
        float4 acc = make_float4(0.f, 0.f, 0.f, 0.f);
        #pragma unroll
        for (int kk = 0; kk < 8; kk++) {
            const int k = kk * 2 + half;
            const float4 v = ((const float4*)(entity_emb + eg_s[g][k] * 64))[c];
            const float a = attn_g[g][k];
            acc.x += a * v.x; acc.y += a * v.y; acc.z += a * v.z; acc.w += a * v.w;
        }
        acc.x += __shfl_xor_sync(0xffffffffu, acc.x, 16);
        acc.y += __shfl_xor_sync(0xffffffffu, acc.y, 16);
        acc.z += __shfl_xor_sync(0xffffffffu, acc.z, 16);
        acc.w += __shfl_xor_sync(0xffffffffu, acc.w, 16);
        if (half == 0) {
            const float4 sv = ((const float4*)(entity_emb + self_s[g] * 64))[c];
            ((float4*)x_s[g])[c] = make_float4(sv.x + acc.x, sv.y + acc.y,
                                               sv.z + acc.z, sv.w + acc.w);
        }
    }
    if (w >= 6) {   // 5th group: g = 32 (w=6), 33 (w=7)
        const int g = 26 + w;
        float4 acc = make_float4(0.f, 0.f, 0.f, 0.f);
        #pragma unroll
        for (int kk = 0; kk < 8; kk++) {
            const int k = kk * 2 + half;
            const float4 v = ((const float4*)(entity_emb + eg_s[g][k] * 64))[c];
            const float a = attn_g[g][k];
            acc.x += a * v.x; acc.y += a * v.y; acc.z += a * v.z; acc.w += a * v.w;
        }
        acc.x += __shfl_xor_sync(0xffffffffu, acc.x, 16);
        acc.y += __shfl_xor_sync(0xffffffffu, acc.y, 16);
        acc.z += __shfl_xor_sync(0xffffffffu, acc.z, 16);
        acc.w += __shfl_xor_sync(0xffffffffu, acc.w, 16);
        if (half == 0) {
            const float4 sv = ((const float4*)(entity_emb + self_s[g] * 64))[c];
            ((float4*)x_s[g])[c] = make_float4(sv.x + acc.x, sv.y + acc.y,
                                               sv.z + acc.z, sv.w + acc.w);
        }
    }
    __syncthreads();

    // ---- P5: 34 matvecs in ONE W pass; warp w -> slots 4w..4w+3,
    //          warps 6,7 carry slots 32,33 as 5th accumulator. In-place h. ----
    {
        const float* xflat = &x_s[0][0];
        const float bl = b0[lane], bh = b0[lane + 32];
        float al[4], ah[4];
        #pragma unroll
        for (int q = 0; q < 4; q++) { al[q] = bl; ah[q] = bh; }
        float al5 = bl, ah5 = bh;
        const int f4 = w * 4;
        const int f5 = 26 + w;                 // valid for w>=6
        const bool has5 = (w >= 6);
        #pragma unroll
        for (int dd = 0; dd < 16; dd++) {
            const float4 wl = W0_s[lane * W0PAD + dd];
            const float4 wh = W0_s[(lane + 32) * W0PAD + dd];
            #pragma unroll
            for (int q = 0; q < 4; q++) {
                const float4 xv = ((const float4*)(xflat + (f4 + q) * 64))[dd];
                al[q] += xv.x*wl.x + xv.y*wl.y + xv.z*wl.z + xv.w*wl.w;
                ah[q] += xv.x*wh.x + xv.y*wh.y + xv.z*wh.z + xv.w*wh.w;
            }
            if (has5) {
                const float4 xv = ((const float4*)(xflat + f5 * 64))[dd];
                al5 += xv.x*wl.x + xv.y*wl.y + xv.z*wl.z + xv.w*wl.w;
                ah5 += xv.x*wh.x + xv.y*wh.y + xv.z*wh.z + xv.w*wh.w;
            }
        }
        #pragma unroll
        for (int q = 0; q < 4; q++) {
            x_s[f4 + q][lane]      = fmaxf(al[q], 0.f);
            x_s[f4 + q][lane + 32] = fmaxf(ah[q], 0.f);
        }
        if (has5) {
            x_s[f5][lane]      = fmaxf(al5, 0.f);
            x_s[f5][lane + 32] = fmaxf(ah5, 0.f);
        }
    }
    __syncthreads();

    // ---- P6: layer-1 hop-0 combine, tanh matvec, score ----
    if (t < 128) {
        const int elem = t >> 6, d = t & 63;
        float agg = 0.f;
        #pragma unroll
        for (int k = 0; k < 16; k++) agg += attn_g[32 + elem][k] * x_s[elem * 16 + k][d];
        xf_s[elem][d] = x_s[32 + elem][d] + agg;
    }
    __syncthreads();
    if (t < 128) {
        const int elem = t >> 6, d = t & 63;
        float acc = b1[d];
        const float4* w1r = (const float4*)(W1 + d * 64);
        const float4* x0v = (const float4*)xf_s[elem];
        #pragma unroll
        for (int dd = 0; dd < 16; dd++) {
            const float4 xv = x0v[dd];
            const float4 wv = w1r[dd];
            acc += xv.x * wv.x + xv.y * wv.y + xv.z * wv.z + xv.w * wv.w;
        }
        const float item = tanhf(acc);
        float p = ue_s[elem][d] * item;
        #pragma unroll
        for (int o = 16; o; o >>= 1) p += __shfl_xor_sync(0xffffffffu, p, o);
        if (lane == 0) red_s[elem][w & 1] = p;
    }
    __syncthreads();
    if (t < 2) {
        const int bi = 2 * b + t;
        if (bi < B) {
            const float s = red_s[t][0] + red_s[t][1];
            out[bi] = 1.f / (1.f + __expf(-s));
        }
    }
}

extern "C" void kernel_launch(void* const* d_in, const int* in_sizes, int n_in,
                              void* d_out, int out_size) {
    const int*   u_ids        = (const int*)d_in[0];
    const int*   i_ids        = (const int*)d_in[1];
    const int*   adj_entity   = (const int*)d_in[2];
    const int*   adj_relation = (const int*)d_in[3];
    const float* user_emb     = (const float*)d_in[4];
    const float* entity_emb   = (const float*)d_in[5];
    const float* relation_emb = (const float*)d_in[6];
    const float* W0           = (const float*)d_in[7];
    const float* b0           = (const float*)d_in[8];
    const float* W1           = (const float*)d_in[9];
    const float* b1           = (const float*)d_in[10];
    float* out = (float*)d_out;

    const int B = in_sizes[1];
    const int grid = (B + 1) / 2;
    kgnn_kernel<<<grid, 256>>>(u_ids, i_ids, adj_entity, adj_relation,
                               user_emb, entity_emb, relation_emb,
                               W0, b0, W1, b1, out, B);
}